// round 16
// baseline (speedup 1.0000x reference)
#include <cuda_runtime.h>

#define N_NODES 200000
#define N_EDGES 1000000
#define INDIM   64
#define HDIM    128
#define N_MOLS  8000
#define BN_EPS  1e-5f
#define SLOPE   0.01f

typedef unsigned long long ull;

// ---------------- packed fp32x2 helpers (Blackwell FFMA2) ----------------
__device__ __forceinline__ ull ffma2(ull a, ull b, ull c) {
    ull d;
    asm("fma.rn.f32x2 %0, %1, %2, %3;" : "=l"(d) : "l"(a), "l"(b), "l"(c));
    return d;
}
__device__ __forceinline__ ull pack2(float lo, float hi) {
    ull d;
    asm("mov.b64 %0, {%1, %2};" : "=l"(d) : "f"(lo), "f"(hi));
    return d;
}
__device__ __forceinline__ float2 unpack2(ull v) {
    float lo, hi;
    asm("mov.b64 {%0, %1}, %2;" : "=f"(lo), "=f"(hi) : "l"(v));
    return make_float2(lo, hi);
}

// ---------------- scratch (static device globals; no allocation) ----------------
static __device__ float g_h1[(size_t)N_NODES * HDIM];
static __device__ float g_h2[(size_t)N_NODES * HDIM];
static __device__ float g_h3[(size_t)N_NODES * HDIM];
static __device__ float g_agg[(size_t)N_NODES * HDIM];
static __device__ float g_pool[(size_t)N_MOLS * HDIM];
static __device__ float g_dotv[N_NODES];
static __device__ float g_Wt1[HDIM * 64];
static __device__ float g_Wt2[HDIM * HDIM];
static __device__ float g_Wt3[HDIM * HDIM];
static __device__ int   g_src[N_EDGES];
static __device__ int   g_dst[N_EDGES];
static __device__ int   g_bat[N_NODES];
static __device__ int   g_deg[N_NODES];
static __device__ int   g_off[N_NODES + 1];
static __device__ int   g_cur[N_NODES];
static __device__ int   g_bsum[1024];
static __device__ int   g_csr_src[N_EDGES];
static __device__ float g_csr_attr[(size_t)N_EDGES * 16];

// ---------------- convert (dtype detect inline) + dst histogram + pool zero ----------------
__global__ __launch_bounds__(256)
void convert_hist_kernel(const void* __restrict__ ei, const void* __restrict__ batch,
                         int E, int N)
{
    __shared__ int s_is64;
    if (threadIdx.x == 0) {
        const int* p = (const int*)ei;
        int nz = 0;
        for (int i = 0; i < 64; i++) nz |= p[2 * i + 1];   // int64 high words == 0
        s_is64 = (nz == 0);
    }
    __syncthreads();
    const int is64 = s_is64;
    const int tid = blockIdx.x * blockDim.x + threadIdx.x;
    const int stride = gridDim.x * blockDim.x;
    const long long* e64 = (const long long*)ei;
    const int*       e32 = (const int*)ei;
    const long long* b64 = (const long long*)batch;
    const int*       b32 = (const int*)batch;
    for (int e = tid; e < E; e += stride) {
        int s, d;
        if (is64) { s = (int)e64[e]; d = (int)e64[E + e]; }
        else      { s = e32[e];      d = e32[E + e]; }
        g_src[e] = s;
        g_dst[e] = d;
        atomicAdd(&g_deg[d], 1);
    }
    for (int n = tid; n < N; n += stride)
        g_bat[n] = is64 ? (int)b64[n] : b32[n];
    float4 z = make_float4(0.f, 0.f, 0.f, 0.f);
    for (int i = tid; i < N_MOLS * 32; i += stride)
        reinterpret_cast<float4*>(g_pool)[i] = z;
}

// ---------------- scan stage 1 ----------------
__global__ __launch_bounds__(256)
void scan_k1(int N)
{
    __shared__ int s[256];
    const int t = threadIdx.x;
    const int i = blockIdx.x * 256 + t;
    int v = (i < N) ? g_deg[i] : 0;
    s[t] = v;
    __syncthreads();
#pragma unroll
    for (int d = 1; d < 256; d <<= 1) {
        int x = (t >= d) ? s[t - d] : 0;
        __syncthreads();
        if (t >= d) s[t] += x;
        __syncthreads();
    }
    if (i < N) {
        g_off[i] = s[t] - v;
        g_deg[i] = 0;
    }
    if (t == 255) g_bsum[blockIdx.x] = s[t];
}

// ---------------- scan stage 2 (fused fixup) ----------------
__global__ __launch_bounds__(256)
void scan_k2f(int N, int E)
{
    __shared__ int r[256];
    const int t = threadIdx.x;
    int acc = 0;
    for (int i = t; i < blockIdx.x; i += 256) acc += g_bsum[i];
    r[t] = acc;
    __syncthreads();
#pragma unroll
    for (int d = 128; d; d >>= 1) {
        if (t < d) r[t] += r[t + d];
        __syncthreads();
    }
    const int prefix = r[0];
    const int i = blockIdx.x * 256 + t;
    if (i < N) {
        int o = g_off[i] + prefix;
        g_off[i] = o;
        g_cur[i] = o;
    }
    if (i == 0) g_off[N] = E;
}

// ---------------- scatter: permute src + attr into CSR order ----------------
__global__ __launch_bounds__(256)
void scatter_kernel(const float* __restrict__ eattr, int E)
{
    const int tid = blockIdx.x * blockDim.x + threadIdx.x;
    const int stride = gridDim.x * blockDim.x;
    for (int e = tid; e < E; e += stride) {
        int d = g_dst[e];
        int p = atomicAdd(&g_cur[d], 1);
        g_csr_src[p] = g_src[e];
        const float4* s4 = reinterpret_cast<const float4*>(eattr + (size_t)e * 16);
        float4* d4 = reinterpret_cast<float4*>(g_csr_attr + (size_t)p * 16);
        d4[0] = s4[0]; d4[1] = s4[1]; d4[2] = s4[2]; d4[3] = s4[3];
    }
}

// ---------------- CSR edge aggregation over a 64-dim slice ----------------
// 2-edge shfl, 128-thr blocks; minBlocks=9 caps regs at 56 for higher occupancy.
// Writes agg[n] = x[n] + sum_of_messages.
template <int STRIDE>
__global__ __launch_bounds__(128, 9)
void edge_csr_half(const float* __restrict__ xin,
                   const float* __restrict__ We,    // [STRIDE,16]
                   const float* __restrict__ be,    // [STRIDE]
                   float* __restrict__ agg,         // [N,STRIDE]
                   int N)
{
    const int lane  = threadIdx.x & 31;
    const int warp  = (blockIdx.x * blockDim.x + threadIdx.x) >> 5;
    const int nwarp = (gridDim.x * blockDim.x) >> 5;
    const int d0    = blockIdx.y * 64 + 2 * lane;

    float2 w[16];
#pragma unroll
    for (int k = 0; k < 16; k++)
        w[k] = make_float2(We[(d0 + 0) * 16 + k], We[(d0 + 1) * 16 + k]);
    const float2 bev = make_float2(be[d0], be[d0 + 1]);

    for (int n = warp; n < N; n += nwarp) {
        const int beg = g_off[n], end = g_off[n + 1];
        float2 acc = *reinterpret_cast<const float2*>(xin + (size_t)n * STRIDE + d0);
        int p = beg;
        for (; p + 2 <= end; p += 2) {
            int s0 = g_csr_src[p];
            int s1 = g_csr_src[p + 1];
            float a = g_csr_attr[(size_t)p * 16 + lane];
            float2 xv0 = *reinterpret_cast<const float2*>(xin + (size_t)s0 * STRIDE + d0);
            float2 xv1 = *reinterpret_cast<const float2*>(xin + (size_t)s1 * STRIDE + d0);
            float2 m0 = bev, m1 = bev;
#pragma unroll
            for (int k = 0; k < 16; k++) {
                float ak0 = __shfl_sync(0xffffffffu, a, k);
                float ak1 = __shfl_sync(0xffffffffu, a, 16 + k);
                m0.x = fmaf(w[k].x, ak0, m0.x);
                m0.y = fmaf(w[k].y, ak0, m0.y);
                m1.x = fmaf(w[k].x, ak1, m1.x);
                m1.y = fmaf(w[k].y, ak1, m1.y);
            }
            acc.x += fmaxf(xv0.x + m0.x, 0.f) + fmaxf(xv1.x + m1.x, 0.f);
            acc.y += fmaxf(xv0.y + m0.y, 0.f) + fmaxf(xv1.y + m1.y, 0.f);
        }
        if (p < end) {
            int s0 = g_csr_src[p];
            float a = g_csr_attr[(size_t)p * 16 + (lane & 15)];
            float2 xv0 = *reinterpret_cast<const float2*>(xin + (size_t)s0 * STRIDE + d0);
            float2 m0 = bev;
#pragma unroll
            for (int k = 0; k < 16; k++) {
                float ak0 = __shfl_sync(0xffffffffu, a, k);
                m0.x = fmaf(w[k].x, ak0, m0.x);
                m0.y = fmaf(w[k].y, ak0, m0.y);
            }
            acc.x += fmaxf(xv0.x + m0.x, 0.f);
            acc.y += fmaxf(xv0.y + m0.y, 0.f);
        }
        *reinterpret_cast<float2*>(agg + (size_t)n * STRIDE + d0) = acc;
    }
}

// ---------------- transpose all three W matrices ----------------
__global__ void transpose_all(const float* __restrict__ W1, const float* __restrict__ W2,
                              const float* __restrict__ W3)
{
    int idx = blockIdx.x * blockDim.x + threadIdx.x;
    if (idx < HDIM * 64) {
        int j = idx / 64, k = idx - j * 64;
        g_Wt1[k * HDIM + j] = W1[idx];
    }
    if (idx < HDIM * HDIM) {
        int j = idx >> 7, k = idx & 127;
        g_Wt2[k * HDIM + j] = W2[idx];
        g_Wt3[k * HDIM + j] = W3[idx];
    }
}

// ---------------- node GEMM v2 + fused head partial ----------------
template <int DIN, bool ACCUM>
__global__ __launch_bounds__(256)
void node_v2(const float* __restrict__ agg,   // [N,DIN] = x + messages
             const float* __restrict__ Wt,    // [DIN][128] k-major
             const float* __restrict__ b,
             const float* __restrict__ gamma,
             const float* __restrict__ beta,
             const float* __restrict__ rmean,
             const float* __restrict__ rvar,
             const float* __restrict__ WlSeg,  // [128] head weights for this layer
             float* __restrict__ dotv,         // [N]
             float* __restrict__ hout,         // [N,128]
             int nNodes)
{
    __shared__ float xs[32 * 132];
    __shared__ float ws[32 * 128];
    const int tx = threadIdx.x;
    const int cg = tx & 15;
    const int ng = tx >> 4;
    const int base = blockIdx.x * 128;
    const int n0 = ng * 8;
    const int jA = cg * 4;
    const int jB = 64 + cg * 4;

    ull acc[4][8];
#pragma unroll
    for (int np = 0; np < 4; np++)
#pragma unroll
        for (int j = 0; j < 8; j++) acc[np][j] = 0ull;

    for (int kb = 0; kb < DIN; kb += 32) {
#pragma unroll
        for (int r = 0; r < 16; r++) {
            int idx = r * 256 + tx;
            int k = idx & 31;
            int n = idx >> 5;
            int node = base + n;
            float v = 0.f;
            if (node < nNodes)
                v = agg[(size_t)node * DIN + kb + k];
            xs[k * 132 + n] = v;
        }
#pragma unroll
        for (int r = 0; r < 16; r++) {
            int idx = r * 256 + tx;
            ws[idx] = Wt[(size_t)(kb + (idx >> 7)) * HDIM + (idx & 127)];
        }
        __syncthreads();

#pragma unroll 8
        for (int k = 0; k < 32; k++) {
            const ulonglong2* xp = reinterpret_cast<const ulonglong2*>(xs + k * 132 + n0);
            ulonglong2 xa = xp[0];
            ulonglong2 xb = xp[1];
            ull xq0 = xa.x, xq1 = xa.y, xq2 = xb.x, xq3 = xb.y;
            float4 w0 = *reinterpret_cast<const float4*>(ws + k * 128 + jA);
            float4 w1 = *reinterpret_cast<const float4*>(ws + k * 128 + jB);
            ull wd[8];
            wd[0] = pack2(w0.x, w0.x); wd[1] = pack2(w0.y, w0.y);
            wd[2] = pack2(w0.z, w0.z); wd[3] = pack2(w0.w, w0.w);
            wd[4] = pack2(w1.x, w1.x); wd[5] = pack2(w1.y, w1.y);
            wd[6] = pack2(w1.z, w1.z); wd[7] = pack2(w1.w, w1.w);
#pragma unroll
            for (int j = 0; j < 8; j++) {
                acc[0][j] = ffma2(xq0, wd[j], acc[0][j]);
                acc[1][j] = ffma2(xq1, wd[j], acc[1][j]);
                acc[2][j] = ffma2(xq2, wd[j], acc[2][j]);
                acc[3][j] = ffma2(xq3, wd[j], acc[3][j]);
            }
        }
        __syncthreads();
    }

    float sc[8], sh[8];
#pragma unroll
    for (int jj = 0; jj < 8; jj++) {
        int j = (jj < 4) ? (jA + jj) : (jB + jj - 4);
        float scale = gamma[j] * rsqrtf(rvar[j] + BN_EPS);
        sc[jj] = scale;
        sh[jj] = b[j] * scale + beta[j] - rmean[j] * scale;
    }
    const float4 wlA = *reinterpret_cast<const float4*>(WlSeg + jA);
    const float4 wlB = *reinterpret_cast<const float4*>(WlSeg + jB);

    float dotp[8];
#pragma unroll
    for (int q = 0; q < 8; q++) dotp[q] = 0.f;

#pragma unroll
    for (int np = 0; np < 4; np++) {
        int na = base + n0 + 2 * np;
        int nb = na + 1;
        float2 t[8];
#pragma unroll
        for (int j = 0; j < 8; j++) t[j] = unpack2(acc[np][j]);
        if (na < nNodes) {
            float4 oA, oB;
            float y;
            y = t[0].x * sc[0] + sh[0]; oA.x = (y > 0.f) ? y : SLOPE * y;
            y = t[1].x * sc[1] + sh[1]; oA.y = (y > 0.f) ? y : SLOPE * y;
            y = t[2].x * sc[2] + sh[2]; oA.z = (y > 0.f) ? y : SLOPE * y;
            y = t[3].x * sc[3] + sh[3]; oA.w = (y > 0.f) ? y : SLOPE * y;
            y = t[4].x * sc[4] + sh[4]; oB.x = (y > 0.f) ? y : SLOPE * y;
            y = t[5].x * sc[5] + sh[5]; oB.y = (y > 0.f) ? y : SLOPE * y;
            y = t[6].x * sc[6] + sh[6]; oB.z = (y > 0.f) ? y : SLOPE * y;
            y = t[7].x * sc[7] + sh[7]; oB.w = (y > 0.f) ? y : SLOPE * y;
            *reinterpret_cast<float4*>(hout + (size_t)na * HDIM + jA) = oA;
            *reinterpret_cast<float4*>(hout + (size_t)na * HDIM + jB) = oB;
            dotp[2 * np + 0] = oA.x * wlA.x + oA.y * wlA.y + oA.z * wlA.z + oA.w * wlA.w
                             + oB.x * wlB.x + oB.y * wlB.y + oB.z * wlB.z + oB.w * wlB.w;
        }
        if (nb < nNodes) {
            float4 oA, oB;
            float y;
            y = t[0].y * sc[0] + sh[0]; oA.x = (y > 0.f) ? y : SLOPE * y;
            y = t[1].y * sc[1] + sh[1]; oA.y = (y > 0.f) ? y : SLOPE * y;
            y = t[2].y * sc[2] + sh[2]; oA.z = (y > 0.f) ? y : SLOPE * y;
            y = t[3].y * sc[3] + sh[3]; oA.w = (y > 0.f) ? y : SLOPE * y;
            y = t[4].y * sc[4] + sh[4]; oB.x = (y > 0.f) ? y : SLOPE * y;
            y = t[5].y * sc[5] + sh[5]; oB.y = (y > 0.f) ? y : SLOPE * y;
            y = t[6].y * sc[6] + sh[6]; oB.z = (y > 0.f) ? y : SLOPE * y;
            y = t[7].y * sc[7] + sh[7]; oB.w = (y > 0.f) ? y : SLOPE * y;
            *reinterpret_cast<float4*>(hout + (size_t)nb * HDIM + jA) = oA;
            *reinterpret_cast<float4*>(hout + (size_t)nb * HDIM + jB) = oB;
            dotp[2 * np + 1] = oA.x * wlA.x + oA.y * wlA.y + oA.z * wlA.z + oA.w * wlA.w
                             + oB.x * wlB.x + oB.y * wlB.y + oB.z * wlB.z + oB.w * wlB.w;
        }
    }

#pragma unroll
    for (int q = 0; q < 8; q++) {
#pragma unroll
        for (int o = 1; o < 16; o <<= 1)
            dotp[q] += __shfl_xor_sync(0xffffffffu, dotp[q], o);
    }
    if (cg == 0) {
#pragma unroll
        for (int q = 0; q < 8; q++) {
            int node = base + n0 + q;
            if (node < nNodes) {
                if (ACCUM) dotv[node] += dotp[q];
                else       dotv[node]  = dotp[q];
            }
        }
    }
}

// ---------------- pool: segment_sum(h3, batch) ----------------
__global__ __launch_bounds__(256)
void pool_kernel(const float* __restrict__ h3,
                 const int* __restrict__ batch,
                 float* __restrict__ pool,
                 int N)
{
    const int total = N * 32;
    for (int idx = blockIdx.x * blockDim.x + threadIdx.x; idx < total;
         idx += gridDim.x * blockDim.x) {
        int n = idx >> 5;
        int c = idx & 31;
        int mol = batch[n];
        float4 v = reinterpret_cast<const float4*>(h3)[(size_t)n * 32 + c];
        atomicAdd(reinterpret_cast<float4*>(pool + (size_t)mol * 128) + c, v);
    }
}

// ---------------- head: out[n] = sigmoid(dotv[n] + Wl4 . pool[batch[n]] + bl) ----------------
__global__ __launch_bounds__(256)
void final_kernel(const float* __restrict__ dotv,
                  const float* __restrict__ pool,
                  const int* __restrict__ batch,
                  const float* __restrict__ Wl, const float* __restrict__ bl,
                  float* __restrict__ out, int N)
{
    const int lane  = threadIdx.x & 31;
    const int warp  = (blockIdx.x * blockDim.x + threadIdx.x) >> 5;
    const int nwarp = (gridDim.x * blockDim.x) >> 5;

    const float4 wl = reinterpret_cast<const float4*>(Wl + 384)[lane];
    const float blv = bl[0];

    for (int n = warp; n < N; n += nwarp) {
        size_t row = (size_t)batch[n];
        float4 v = reinterpret_cast<const float4*>(pool + row * 128)[lane];
        float acc = wl.x * v.x + wl.y * v.y + wl.z * v.z + wl.w * v.w;
#pragma unroll
        for (int o = 16; o; o >>= 1)
            acc += __shfl_xor_sync(0xffffffffu, acc, o);
        if (lane == 0)
            out[n] = 1.f / (1.f + __expf(-(acc + dotv[n] + blv)));
    }
}

// ---------------- launch ----------------
extern "C" void kernel_launch(void* const* d_in, const int* in_sizes, int n_in,
                              void* d_out, int out_size)
{
    const float* x     = (const float*)d_in[0];
    const void*  ei    = d_in[1];
    const float* eattr = (const float*)d_in[2];
    const void*  batch = d_in[3];
    const float* P[3][8];
    for (int i = 0; i < 3; i++)
        for (int k = 0; k < 8; k++)
            P[i][k] = (const float*)d_in[4 + 8 * i + k];
    const float* Wl = (const float*)d_in[28];
    const float* bl = (const float*)d_in[29];
    float* out = (float*)d_out;

    const int E = in_sizes[1] / 2;
    const int N = in_sizes[0] / INDIM;

    float *h1, *h2, *h3, *agg, *pool, *dotv, *Wt1, *Wt2, *Wt3;
    int *bat;
    cudaGetSymbolAddress((void**)&h1,   g_h1);
    cudaGetSymbolAddress((void**)&h2,   g_h2);
    cudaGetSymbolAddress((void**)&h3,   g_h3);
    cudaGetSymbolAddress((void**)&agg,  g_agg);
    cudaGetSymbolAddress((void**)&pool, g_pool);
    cudaGetSymbolAddress((void**)&dotv, g_dotv);
    cudaGetSymbolAddress((void**)&Wt1,  g_Wt1);
    cudaGetSymbolAddress((void**)&Wt2,  g_Wt2);
    cudaGetSymbolAddress((void**)&Wt3,  g_Wt3);
    cudaGetSymbolAddress((void**)&bat,  g_bat);

    const int NODE_BLOCKS = (N + 127) / 128;
    const int NB1 = (N + 255) / 256;
    const dim3 EG1(2368, 1), EG2(2368, 2);   // 128-thread edge blocks

    // ---- CSR build ----
    convert_hist_kernel<<<1184, 256>>>(ei, batch, E, N);
    scan_k1<<<NB1, 256>>>(N);
    scan_k2f<<<NB1, 256>>>(N, E);
    scatter_kernel<<<1184, 256>>>(eattr, E);

    // ---- layer 1 (d_in = 64): head seg 0 ----
    edge_csr_half<64><<<EG1, 128>>>(x, P[0][0], P[0][1], agg, N);
    transpose_all<<<(HDIM * HDIM + 255) / 256, 256>>>(P[0][2], P[1][2], P[2][2]);
    node_v2<64, false><<<NODE_BLOCKS, 256>>>(agg, Wt1, P[0][3], P[0][4], P[0][5],
                                             P[0][6], P[0][7], Wl + 0, dotv, h1, N);

    // ---- layer 2 (d_in = 128): head seg 1 ----
    edge_csr_half<128><<<EG2, 128>>>(h1, P[1][0], P[1][1], agg, N);
    node_v2<128, true><<<NODE_BLOCKS, 256>>>(agg, Wt2, P[1][3], P[1][4], P[1][5],
                                             P[1][6], P[1][7], Wl + 128, dotv, h2, N);

    // ---- layer 3 (d_in = 128): head seg 2 ----
    edge_csr_half<128><<<EG2, 128>>>(h2, P[2][0], P[2][1], agg, N);
    node_v2<128, true><<<NODE_BLOCKS, 256>>>(agg, Wt3, P[2][3], P[2][4], P[2][5],
                                             P[2][6], P[2][7], Wl + 256, dotv, h3, N);

    // ---- pool + head ----
    pool_kernel<<<1184, 256>>>(h3, bat, pool, N);
    final_kernel<<<592, 256>>>(dotv, pool, bat, Wl, bl, out, N);
}

// round 17
// speedup vs baseline: 1.1297x; 1.1297x over previous
#include <cuda_runtime.h>

#define N_NODES 200000
#define N_EDGES 1000000
#define INDIM   64
#define HDIM    128
#define N_MOLS  8000
#define BN_EPS  1e-5f
#define SLOPE   0.01f

typedef unsigned long long ull;

// ---------------- packed fp32x2 helpers (Blackwell FFMA2) ----------------
__device__ __forceinline__ ull ffma2(ull a, ull b, ull c) {
    ull d;
    asm("fma.rn.f32x2 %0, %1, %2, %3;" : "=l"(d) : "l"(a), "l"(b), "l"(c));
    return d;
}
__device__ __forceinline__ ull pack2(float lo, float hi) {
    ull d;
    asm("mov.b64 %0, {%1, %2};" : "=l"(d) : "f"(lo), "f"(hi));
    return d;
}
__device__ __forceinline__ float2 unpack2(ull v) {
    float lo, hi;
    asm("mov.b64 {%0, %1}, %2;" : "=f"(lo), "=f"(hi) : "l"(v));
    return make_float2(lo, hi);
}

// ---------------- scratch (static device globals; no allocation) ----------------
static __device__ float g_h1[(size_t)N_NODES * HDIM];
static __device__ float g_h2[(size_t)N_NODES * HDIM];
static __device__ float g_h3[(size_t)N_NODES * HDIM];
static __device__ float g_agg[(size_t)N_NODES * HDIM];
static __device__ float g_dotv[N_NODES];
static __device__ float g_Wt1[HDIM * 64];
static __device__ float g_Wt2[HDIM * HDIM];
static __device__ float g_Wt3[HDIM * HDIM];
static __device__ int   g_src[N_EDGES];
static __device__ int   g_dst[N_EDGES];
static __device__ int   g_bat[N_NODES];
static __device__ int   g_deg[N_NODES];
static __device__ int   g_off[N_NODES + 1];
static __device__ int   g_cur[N_NODES];
static __device__ int   g_bsum[1024];
static __device__ int   g_csr_src[N_EDGES];
static __device__ float g_csr_attr[(size_t)N_EDGES * 16];

// ---------------- convert (dtype detect inline) + dst histogram ----------------
__global__ __launch_bounds__(256)
void convert_hist_kernel(const void* __restrict__ ei, const void* __restrict__ batch,
                         int E, int N)
{
    __shared__ int s_is64;
    if (threadIdx.x == 0) {
        const int* p = (const int*)ei;
        int nz = 0;
        for (int i = 0; i < 64; i++) nz |= p[2 * i + 1];   // int64 high words == 0
        s_is64 = (nz == 0);
    }
    __syncthreads();
    const int is64 = s_is64;
    const int tid = blockIdx.x * blockDim.x + threadIdx.x;
    const int stride = gridDim.x * blockDim.x;
    const long long* e64 = (const long long*)ei;
    const int*       e32 = (const int*)ei;
    const long long* b64 = (const long long*)batch;
    const int*       b32 = (const int*)batch;
    for (int e = tid; e < E; e += stride) {
        int s, d;
        if (is64) { s = (int)e64[e]; d = (int)e64[E + e]; }
        else      { s = e32[e];      d = e32[E + e]; }
        g_src[e] = s;
        g_dst[e] = d;
        atomicAdd(&g_deg[d], 1);
    }
    for (int n = tid; n < N; n += stride)
        g_bat[n] = is64 ? (int)b64[n] : b32[n];
}

// ---------------- scan stage 1 ----------------
__global__ __launch_bounds__(256)
void scan_k1(int N)
{
    __shared__ int s[256];
    const int t = threadIdx.x;
    const int i = blockIdx.x * 256 + t;
    int v = (i < N) ? g_deg[i] : 0;
    s[t] = v;
    __syncthreads();
#pragma unroll
    for (int d = 1; d < 256; d <<= 1) {
        int x = (t >= d) ? s[t - d] : 0;
        __syncthreads();
        if (t >= d) s[t] += x;
        __syncthreads();
    }
    if (i < N) {
        g_off[i] = s[t] - v;
        g_deg[i] = 0;
    }
    if (t == 255) g_bsum[blockIdx.x] = s[t];
}

// ---------------- scan stage 2 (fused fixup) ----------------
__global__ __launch_bounds__(256)
void scan_k2f(int N, int E)
{
    __shared__ int r[256];
    const int t = threadIdx.x;
    int acc = 0;
    for (int i = t; i < blockIdx.x; i += 256) acc += g_bsum[i];
    r[t] = acc;
    __syncthreads();
#pragma unroll
    for (int d = 128; d; d >>= 1) {
        if (t < d) r[t] += r[t + d];
        __syncthreads();
    }
    const int prefix = r[0];
    const int i = blockIdx.x * 256 + t;
    if (i < N) {
        int o = g_off[i] + prefix;
        g_off[i] = o;
        g_cur[i] = o;
    }
    if (i == 0) g_off[N] = E;
}

// ---------------- scatter: permute src + attr into CSR order ----------------
__global__ __launch_bounds__(256)
void scatter_kernel(const float* __restrict__ eattr, int E)
{
    const int tid = blockIdx.x * blockDim.x + threadIdx.x;
    const int stride = gridDim.x * blockDim.x;
    for (int e = tid; e < E; e += stride) {
        int d = g_dst[e];
        int p = atomicAdd(&g_cur[d], 1);
        g_csr_src[p] = g_src[e];
        const float4* s4 = reinterpret_cast<const float4*>(eattr + (size_t)e * 16);
        float4* d4 = reinterpret_cast<float4*>(g_csr_attr + (size_t)p * 16);
        d4[0] = s4[0]; d4[1] = s4[1]; d4[2] = s4[2]; d4[3] = s4[3];
    }
}

// ---------------- CSR edge aggregation over a 64-dim slice (2-edge shfl, 128-thr blocks) ----------------
// Writes agg[n] = x[n] + sum_of_messages.
template <int STRIDE>
__global__ __launch_bounds__(128)
void edge_csr_half(const float* __restrict__ xin,
                   const float* __restrict__ We,    // [STRIDE,16]
                   const float* __restrict__ be,    // [STRIDE]
                   float* __restrict__ agg,         // [N,STRIDE]
                   int N)
{
    const int lane  = threadIdx.x & 31;
    const int warp  = (blockIdx.x * blockDim.x + threadIdx.x) >> 5;
    const int nwarp = (gridDim.x * blockDim.x) >> 5;
    const int d0    = blockIdx.y * 64 + 2 * lane;

    float2 w[16];
#pragma unroll
    for (int k = 0; k < 16; k++)
        w[k] = make_float2(We[(d0 + 0) * 16 + k], We[(d0 + 1) * 16 + k]);
    const float2 bev = make_float2(be[d0], be[d0 + 1]);

    for (int n = warp; n < N; n += nwarp) {
        const int beg = g_off[n], end = g_off[n + 1];
        float2 acc = *reinterpret_cast<const float2*>(xin + (size_t)n * STRIDE + d0);
        int p = beg;
        for (; p + 2 <= end; p += 2) {
            int s0 = g_csr_src[p];
            int s1 = g_csr_src[p + 1];
            float a = g_csr_attr[(size_t)p * 16 + lane];
            float2 xv0 = *reinterpret_cast<const float2*>(xin + (size_t)s0 * STRIDE + d0);
            float2 xv1 = *reinterpret_cast<const float2*>(xin + (size_t)s1 * STRIDE + d0);
            float2 m0 = bev, m1 = bev;
#pragma unroll
            for (int k = 0; k < 16; k++) {
                float ak0 = __shfl_sync(0xffffffffu, a, k);
                float ak1 = __shfl_sync(0xffffffffu, a, 16 + k);
                m0.x = fmaf(w[k].x, ak0, m0.x);
                m0.y = fmaf(w[k].y, ak0, m0.y);
                m1.x = fmaf(w[k].x, ak1, m1.x);
                m1.y = fmaf(w[k].y, ak1, m1.y);
            }
            acc.x += fmaxf(xv0.x + m0.x, 0.f) + fmaxf(xv1.x + m1.x, 0.f);
            acc.y += fmaxf(xv0.y + m0.y, 0.f) + fmaxf(xv1.y + m1.y, 0.f);
        }
        if (p < end) {
            int s0 = g_csr_src[p];
            float a = g_csr_attr[(size_t)p * 16 + (lane & 15)];
            float2 xv0 = *reinterpret_cast<const float2*>(xin + (size_t)s0 * STRIDE + d0);
            float2 m0 = bev;
#pragma unroll
            for (int k = 0; k < 16; k++) {
                float ak0 = __shfl_sync(0xffffffffu, a, k);
                m0.x = fmaf(w[k].x, ak0, m0.x);
                m0.y = fmaf(w[k].y, ak0, m0.y);
            }
            acc.x += fmaxf(xv0.x + m0.x, 0.f);
            acc.y += fmaxf(xv0.y + m0.y, 0.f);
        }
        *reinterpret_cast<float2*>(agg + (size_t)n * STRIDE + d0) = acc;
    }
}

// ---------------- transpose all three W matrices ----------------
__global__ void transpose_all(const float* __restrict__ W1, const float* __restrict__ W2,
                              const float* __restrict__ W3)
{
    int idx = blockIdx.x * blockDim.x + threadIdx.x;
    if (idx < HDIM * 64) {
        int j = idx / 64, k = idx - j * 64;
        g_Wt1[k * HDIM + j] = W1[idx];
    }
    if (idx < HDIM * HDIM) {
        int j = idx >> 7, k = idx & 127;
        g_Wt2[k * HDIM + j] = W2[idx];
        g_Wt3[k * HDIM + j] = W3[idx];
    }
}

// ---------------- node GEMM v2 + fused head partial ----------------
// dotv[n] (ACCUM? += : =) WlSeg . h[n]  computed from register-resident h.
template <int DIN, bool ACCUM>
__global__ __launch_bounds__(256)
void node_v2(const float* __restrict__ agg,   // [N,DIN] = x + messages
             const float* __restrict__ Wt,    // [DIN][128] k-major
             const float* __restrict__ b,
             const float* __restrict__ gamma,
             const float* __restrict__ beta,
             const float* __restrict__ rmean,
             const float* __restrict__ rvar,
             const float* __restrict__ WlSeg,  // [128] head weights for this layer
             float* __restrict__ dotv,         // [N]
             float* __restrict__ hout,         // [N,128]
             int nNodes)
{
    __shared__ float xs[32 * 132];
    __shared__ float ws[32 * 128];
    const int tx = threadIdx.x;
    const int cg = tx & 15;
    const int ng = tx >> 4;
    const int base = blockIdx.x * 128;
    const int n0 = ng * 8;
    const int jA = cg * 4;
    const int jB = 64 + cg * 4;

    ull acc[4][8];
#pragma unroll
    for (int np = 0; np < 4; np++)
#pragma unroll
        for (int j = 0; j < 8; j++) acc[np][j] = 0ull;

    for (int kb = 0; kb < DIN; kb += 32) {
#pragma unroll
        for (int r = 0; r < 16; r++) {
            int idx = r * 256 + tx;
            int k = idx & 31;
            int n = idx >> 5;
            int node = base + n;
            float v = 0.f;
            if (node < nNodes)
                v = agg[(size_t)node * DIN + kb + k];
            xs[k * 132 + n] = v;
        }
#pragma unroll
        for (int r = 0; r < 16; r++) {
            int idx = r * 256 + tx;
            ws[idx] = Wt[(size_t)(kb + (idx >> 7)) * HDIM + (idx & 127)];
        }
        __syncthreads();

#pragma unroll 8
        for (int k = 0; k < 32; k++) {
            const ulonglong2* xp = reinterpret_cast<const ulonglong2*>(xs + k * 132 + n0);
            ulonglong2 xa = xp[0];
            ulonglong2 xb = xp[1];
            ull xq0 = xa.x, xq1 = xa.y, xq2 = xb.x, xq3 = xb.y;
            float4 w0 = *reinterpret_cast<const float4*>(ws + k * 128 + jA);
            float4 w1 = *reinterpret_cast<const float4*>(ws + k * 128 + jB);
            ull wd[8];
            wd[0] = pack2(w0.x, w0.x); wd[1] = pack2(w0.y, w0.y);
            wd[2] = pack2(w0.z, w0.z); wd[3] = pack2(w0.w, w0.w);
            wd[4] = pack2(w1.x, w1.x); wd[5] = pack2(w1.y, w1.y);
            wd[6] = pack2(w1.z, w1.z); wd[7] = pack2(w1.w, w1.w);
#pragma unroll
            for (int j = 0; j < 8; j++) {
                acc[0][j] = ffma2(xq0, wd[j], acc[0][j]);
                acc[1][j] = ffma2(xq1, wd[j], acc[1][j]);
                acc[2][j] = ffma2(xq2, wd[j], acc[2][j]);
                acc[3][j] = ffma2(xq3, wd[j], acc[3][j]);
            }
        }
        __syncthreads();
    }

    float sc[8], sh[8];
#pragma unroll
    for (int jj = 0; jj < 8; jj++) {
        int j = (jj < 4) ? (jA + jj) : (jB + jj - 4);
        float scale = gamma[j] * rsqrtf(rvar[j] + BN_EPS);
        sc[jj] = scale;
        sh[jj] = b[j] * scale + beta[j] - rmean[j] * scale;
    }
    const float4 wlA = *reinterpret_cast<const float4*>(WlSeg + jA);
    const float4 wlB = *reinterpret_cast<const float4*>(WlSeg + jB);

    float dotp[8];
#pragma unroll
    for (int q = 0; q < 8; q++) dotp[q] = 0.f;

#pragma unroll
    for (int np = 0; np < 4; np++) {
        int na = base + n0 + 2 * np;
        int nb = na + 1;
        float2 t[8];
#pragma unroll
        for (int j = 0; j < 8; j++) t[j] = unpack2(acc[np][j]);
        if (na < nNodes) {
            float4 oA, oB;
            float y;
            y = t[0].x * sc[0] + sh[0]; oA.x = (y > 0.f) ? y : SLOPE * y;
            y = t[1].x * sc[1] + sh[1]; oA.y = (y > 0.f) ? y : SLOPE * y;
            y = t[2].x * sc[2] + sh[2]; oA.z = (y > 0.f) ? y : SLOPE * y;
            y = t[3].x * sc[3] + sh[3]; oA.w = (y > 0.f) ? y : SLOPE * y;
            y = t[4].x * sc[4] + sh[4]; oB.x = (y > 0.f) ? y : SLOPE * y;
            y = t[5].x * sc[5] + sh[5]; oB.y = (y > 0.f) ? y : SLOPE * y;
            y = t[6].x * sc[6] + sh[6]; oB.z = (y > 0.f) ? y : SLOPE * y;
            y = t[7].x * sc[7] + sh[7]; oB.w = (y > 0.f) ? y : SLOPE * y;
            *reinterpret_cast<float4*>(hout + (size_t)na * HDIM + jA) = oA;
            *reinterpret_cast<float4*>(hout + (size_t)na * HDIM + jB) = oB;
            dotp[2 * np + 0] = oA.x * wlA.x + oA.y * wlA.y + oA.z * wlA.z + oA.w * wlA.w
                             + oB.x * wlB.x + oB.y * wlB.y + oB.z * wlB.z + oB.w * wlB.w;
        }
        if (nb < nNodes) {
            float4 oA, oB;
            float y;
            y = t[0].y * sc[0] + sh[0]; oA.x = (y > 0.f) ? y : SLOPE * y;
            y = t[1].y * sc[1] + sh[1]; oA.y = (y > 0.f) ? y : SLOPE * y;
            y = t[2].y * sc[2] + sh[2]; oA.z = (y > 0.f) ? y : SLOPE * y;
            y = t[3].y * sc[3] + sh[3]; oA.w = (y > 0.f) ? y : SLOPE * y;
            y = t[4].y * sc[4] + sh[4]; oB.x = (y > 0.f) ? y : SLOPE * y;
            y = t[5].y * sc[5] + sh[5]; oB.y = (y > 0.f) ? y : SLOPE * y;
            y = t[6].y * sc[6] + sh[6]; oB.z = (y > 0.f) ? y : SLOPE * y;
            y = t[7].y * sc[7] + sh[7]; oB.w = (y > 0.f) ? y : SLOPE * y;
            *reinterpret_cast<float4*>(hout + (size_t)nb * HDIM + jA) = oA;
            *reinterpret_cast<float4*>(hout + (size_t)nb * HDIM + jB) = oB;
            dotp[2 * np + 1] = oA.x * wlA.x + oA.y * wlA.y + oA.z * wlA.z + oA.w * wlA.w
                             + oB.x * wlB.x + oB.y * wlB.y + oB.z * wlB.z + oB.w * wlB.w;
        }
    }

#pragma unroll
    for (int q = 0; q < 8; q++) {
#pragma unroll
        for (int o = 1; o < 16; o <<= 1)
            dotp[q] += __shfl_xor_sync(0xffffffffu, dotp[q], o);
    }
    if (cg == 0) {
#pragma unroll
        for (int q = 0; q < 8; q++) {
            int node = base + n0 + q;
            if (node < nNodes) {
                if (ACCUM) dotv[node] += dotp[q];
                else       dotv[node]  = dotp[q];
            }
        }
    }
}

// ---------------- fused pool+head: warp per molecule (batch is sorted) ----------------
// pool_m = sum of h3 rows in [start,end); pooldot = Wl4 . pool_m (same for all
// nodes of the molecule); out[n] = sigmoid(dotv[n] + pooldot + bl).
__global__ __launch_bounds__(256)
void pool_final_kernel(const float* __restrict__ h3,
                       const int* __restrict__ batch,
                       const float* __restrict__ dotv,
                       const float* __restrict__ Wl, const float* __restrict__ bl,
                       float* __restrict__ out, int N, int nMols)
{
    const int lane  = threadIdx.x & 31;
    const int warp  = (blockIdx.x * blockDim.x + threadIdx.x) >> 5;
    const int nwarp = (gridDim.x * blockDim.x) >> 5;

    const float4 wl = reinterpret_cast<const float4*>(Wl + 384)[lane];
    const float blv = bl[0];

    for (int mol = warp; mol < nMols; mol += nwarp) {
        // lower_bound(batch, mol) — warp-uniform binary search (broadcast loads)
        int lo = 0, hi = N;
        while (lo < hi) {
            int mid = (lo + hi) >> 1;
            if (batch[mid] < mol) lo = mid + 1; else hi = mid;
        }
        const int start = lo;
        hi = N;
        while (lo < hi) {
            int mid = (lo + hi) >> 1;
            if (batch[mid] < mol + 1) lo = mid + 1; else hi = mid;
        }
        const int end = lo;
        if (start >= end) continue;

        // sum h3 rows: lane owns 4 columns (float4 at column lane*4)
        float4 acc = make_float4(0.f, 0.f, 0.f, 0.f);
        for (int n = start; n < end; n++) {
            float4 v = reinterpret_cast<const float4*>(h3 + (size_t)n * HDIM)[lane];
            acc.x += v.x; acc.y += v.y; acc.z += v.z; acc.w += v.w;
        }
        float pd = wl.x * acc.x + wl.y * acc.y + wl.z * acc.z + wl.w * acc.w;
#pragma unroll
        for (int o = 16; o; o >>= 1)
            pd += __shfl_xor_sync(0xffffffffu, pd, o);

        for (int n = start + lane; n < end; n += 32)
            out[n] = 1.f / (1.f + __expf(-(dotv[n] + pd + blv)));
    }
}

// ---------------- launch ----------------
extern "C" void kernel_launch(void* const* d_in, const int* in_sizes, int n_in,
                              void* d_out, int out_size)
{
    const float* x     = (const float*)d_in[0];
    const void*  ei    = d_in[1];
    const float* eattr = (const float*)d_in[2];
    const void*  batch = d_in[3];
    const float* P[3][8];
    for (int i = 0; i < 3; i++)
        for (int k = 0; k < 8; k++)
            P[i][k] = (const float*)d_in[4 + 8 * i + k];
    const float* Wl = (const float*)d_in[28];
    const float* bl = (const float*)d_in[29];
    float* out = (float*)d_out;

    const int E = in_sizes[1] / 2;
    const int N = in_sizes[0] / INDIM;

    float *h1, *h2, *h3, *agg, *dotv, *Wt1, *Wt2, *Wt3;
    int *bat;
    cudaGetSymbolAddress((void**)&h1,   g_h1);
    cudaGetSymbolAddress((void**)&h2,   g_h2);
    cudaGetSymbolAddress((void**)&h3,   g_h3);
    cudaGetSymbolAddress((void**)&agg,  g_agg);
    cudaGetSymbolAddress((void**)&dotv, g_dotv);
    cudaGetSymbolAddress((void**)&Wt1,  g_Wt1);
    cudaGetSymbolAddress((void**)&Wt2,  g_Wt2);
    cudaGetSymbolAddress((void**)&Wt3,  g_Wt3);
    cudaGetSymbolAddress((void**)&bat,  g_bat);

    const int NODE_BLOCKS = (N + 127) / 128;
    const int NB1 = (N + 255) / 256;
    const dim3 EG1(2368, 1), EG2(2368, 2);   // 128-thread edge blocks

    // ---- CSR build ----
    convert_hist_kernel<<<1184, 256>>>(ei, batch, E, N);
    scan_k1<<<NB1, 256>>>(N);
    scan_k2f<<<NB1, 256>>>(N, E);
    scatter_kernel<<<1184, 256>>>(eattr, E);

    // ---- layer 1 (d_in = 64): head seg 0 ----
    edge_csr_half<64><<<EG1, 128>>>(x, P[0][0], P[0][1], agg, N);
    transpose_all<<<(HDIM * HDIM + 255) / 256, 256>>>(P[0][2], P[1][2], P[2][2]);
    node_v2<64, false><<<NODE_BLOCKS, 256>>>(agg, Wt1, P[0][3], P[0][4], P[0][5],
                                             P[0][6], P[0][7], Wl + 0, dotv, h1, N);

    // ---- layer 2 (d_in = 128): head seg 1 ----
    edge_csr_half<128><<<EG2, 128>>>(h1, P[1][0], P[1][1], agg, N);
    node_v2<128, true><<<NODE_BLOCKS, 256>>>(agg, Wt2, P[1][3], P[1][4], P[1][5],
                                             P[1][6], P[1][7], Wl + 128, dotv, h2, N);

    // ---- layer 3 (d_in = 128): head seg 2 ----
    edge_csr_half<128><<<EG2, 128>>>(h2, P[2][0], P[2][1], agg, N);
    node_v2<128, true><<<NODE_BLOCKS, 256>>>(agg, Wt3, P[2][3], P[2][4], P[2][5],
                                             P[2][6], P[2][7], Wl + 256, dotv, h3, N);

    // ---- fused pool + head (warp per molecule, sorted batch) ----
    pool_final_kernel<<<1000, 256>>>(h3, bat, dotv, Wl, bl, out, N, N_MOLS);
}